// round 17
// baseline (speedup 1.0000x reference)
#include <cuda_runtime.h>
#include <cuda_fp16.h>
#include <cstdint>

#define B_SZ 8192
#define I_SZ 256
#define O_SZ 256
#define C_SZ 32
#define FULLMASK 0xFFFFFFFFu
#define MAX_TILES 160
#define TILE_M 64
#define TILE_N 128
#define PREP_NB 32

// ---------------- scratch (device globals; allocation-free) ----------------
__device__ int g_perm[B_SZ];
__device__ int g_offset[C_SZ];
__device__ int g_tiles[MAX_TILES];
__device__ int g_ntiles;
__device__ int g_is64;
__device__ int g_ok64[PREP_NB];
__device__ int g_bh64[PREP_NB * 32];
__device__ int g_bh32[PREP_NB * 32];
__device__ __half g_wq[C_SZ * O_SZ * I_SZ];   // [c][o][i] fp16
__device__ __half g_xh[B_SZ * I_SZ];          // x fp16, UNPERMUTED

__device__ unsigned p_bcnt;
__device__ volatile unsigned p_bgen;

#define GDC_LAUNCH_DEPENDENTS() \
    asm volatile("griddepcontrol.launch_dependents;" ::: "memory")
#define GDC_WAIT() \
    asm volatile("griddepcontrol.wait;" ::: "memory")

// ---------------------------------------------------------------------------
// k_prelude: blocks 0..31 idx sort; 32..543 convert x; 544..799 conv_w
// Every exit path signals PDL dependents.
// ---------------------------------------------------------------------------
__global__ __launch_bounds__(256, 2)
void k_prelude(const float* __restrict__ x,
               const void* __restrict__ idx_ptr,
               const float* __restrict__ weight) {
    __shared__ char sbuf[17152];
    const int b = blockIdx.x;
    const int tid = threadIdx.x;

    if (b >= 32 && b < 544) {
        const int thr = (b - 32) * 256 + tid;
#pragma unroll
        for (int it = 0; it < 2; it++) {
            int g = thr + it * 131072;
            const float4* s = (const float4*)x + (size_t)g * 2;
            float4 v0 = s[0], v1 = s[1];
            union { uint4 u; __half2 h[4]; } P;
            P.h[0] = __float22half2_rn(make_float2(v0.x, v0.y));
            P.h[1] = __float22half2_rn(make_float2(v0.z, v0.w));
            P.h[2] = __float22half2_rn(make_float2(v1.x, v1.y));
            P.h[3] = __float22half2_rn(make_float2(v1.z, v1.w));
            ((uint4*)g_xh)[g] = P.u;
        }
        GDC_LAUNCH_DEPENDENTS();
        return;
    }

    if (b >= 544) {
        __half* sh = (__half*)sbuf;
        const int o = b - 544;
        const float* src = weight + (size_t)o * (I_SZ * C_SZ);
        for (int l = tid; l < I_SZ * C_SZ; l += 256) {
            int i = l >> 5, c = l & 31;
            sh[i * 33 + c] = __float2half_rn(src[l]);
        }
        __syncthreads();
        for (int u = tid; u < (I_SZ * C_SZ) / 4; u += 256) {
            int c = u >> 6, i4 = u & 63;
            union { uint2 uu; __half h[4]; } H;
#pragma unroll
            for (int j = 0; j < 4; j++)
                H.h[j] = sh[(i4 * 4 + j) * 33 + c];
            size_t off = ((size_t)c << 16) + ((size_t)o << 8) + (size_t)i4 * 4;
            *(uint2*)(g_wq + off) = H.uu;
        }
        GDC_LAUNCH_DEPENDENTS();
        return;
    }

    // ======================= prep (blocks 0..31) ===========================
    int* s_h64 = (int*)sbuf;
    int* s_h32 = s_h64 + 256;
    int* s_wb  = s_h32 + 256;
    int* s_vote = s_wb + 256;
    int* s_flag = s_vote + 8;

    const int w = tid >> 5;
    const int lane = tid & 31;
    const int e = b * 256 + tid;

    if (w == 0 && lane < 8) s_vote[lane] = 0;
    s_h64[w * 32 + lane] = 0;
    s_h32[w * 32 + lane] = 0;
    __syncthreads();

    const int v32 = ((const int*)idx_ptr)[e];
    const int2 v64 = ((const int2*)idx_ptr)[e];

    {
        int ok64 = (v64.y == 0) && ((unsigned)v64.x < 32u);
        int allok = __all_sync(FULLMASK, ok64);
        if (lane == 0) s_vote[w] = allok;
    }
    {
        int c = v64.x & 31;
        unsigned m = __match_any_sync(FULLMASK, c);
        if (lane == (__ffs(m) - 1)) s_h64[w * 32 + c] += __popc(m);
    }
    {
        int c = v32 & 31;
        unsigned m = __match_any_sync(FULLMASK, c);
        if (lane == (__ffs(m) - 1)) s_h32[w * 32 + c] += __popc(m);
    }
    __syncthreads();

    if (tid < 32) {
        int t64 = 0, t32 = 0;
#pragma unroll
        for (int w2 = 0; w2 < 8; w2++) {
            t64 += s_h64[w2 * 32 + tid];
            t32 += s_h32[w2 * 32 + tid];
        }
        g_bh64[b * 32 + tid] = t64;
        g_bh32[b * 32 + tid] = t32;
        if (tid == 0) {
            int a = 1;
#pragma unroll
            for (int i = 0; i < 8; i++) a &= s_vote[i];
            g_ok64[b] = a;
        }
    }

    __syncthreads();
    if (tid == 0) {
        unsigned my = p_bgen;
        __threadfence();
        if (atomicAdd(&p_bcnt, 1u) == PREP_NB - 1) {
            p_bcnt = 0;
            __threadfence();
            p_bgen = my + 1;
        } else {
            while (p_bgen == my) {}
            __threadfence();
        }
    }
    __syncthreads();

    if (tid < 32) {
        int v = g_ok64[tid];
        v = __all_sync(FULLMASK, v);
        if (tid == 0) s_flag[0] = v;
    }
    __syncthreads();
    const int is64 = s_flag[0];
    const int* BH = is64 ? g_bh64 : g_bh32;
    int* s_hsel = is64 ? s_h64 : s_h32;

    if (tid < 32) {
        const int c = tid;
        int tot = 0, before = 0;
#pragma unroll
        for (int b2 = 0; b2 < PREP_NB; b2++) {
            int h = BH[b2 * 32 + c];
            if (b2 < b) before += h;
            tot += h;
        }
        int incl = tot;
#pragma unroll
        for (int d = 1; d < 32; d <<= 1) {
            int u = __shfl_up_sync(FULLMASK, incl, d);
            if (lane >= d) incl += u;
        }
        int off = incl - tot;
        int run = off + before;
#pragma unroll
        for (int w2 = 0; w2 < 8; w2++) {
            s_wb[w2 * 32 + c] = run;
            run += s_hsel[w2 * 32 + c];
        }
        if (b == 0) {
            g_offset[c] = off;
            if (c == 0) g_is64 = is64;
            if (lane == 0) {
                int nt = 0;
                for (int cc = 0; cc < 32; cc++) {
                    int cnt = 0;
                    for (int b2 = 0; b2 < PREP_NB; b2++) cnt += BH[b2 * 32 + cc];
                    for (int m = 0; m * TILE_M < cnt; m++) {
                        int rows = min(TILE_M, cnt - m * TILE_M);
                        g_tiles[nt++] = cc | (m << 8) | (rows << 16);
                    }
                }
                g_ntiles = nt;
            }
        }
    }
    __syncthreads();

    {
        int c = is64 ? (v64.x & 31) : (v32 & 31);
        unsigned m = __match_any_sync(FULLMASK, c);
        int rank = __popc(m & ((1u << lane) - 1u));
        int base = s_wb[w * 32 + c];
        g_perm[base + rank] = e;
    }
    GDC_LAUNCH_DEPENDENTS();
}

// ---------------------------------------------------------------------------
// GEMM: 64x128xK256, single-shot residency, per-chunk commit groups,
// progressive wait/compute. PDL: griddepcontrol.wait before global reads.
// ---------------------------------------------------------------------------
#define RB 128
#define A_CH (TILE_M * RB)               // 8192
#define W_CH (TILE_N * RB)               // 16384
#define STAGE (A_CH + W_CH)              // 24576
#define OFF_ROW  0                       // 64 ints
#define OFF_BIAS 256                     // 128 floats
#define OFF_PIPE 768
#define SM_TOTAL (OFF_PIPE + 4 * STAGE)  // 99072

__device__ __forceinline__ uint32_t smem_u32(const void* p) {
    uint32_t a;
    asm("{ .reg .u64 t; cvta.to.shared.u64 t, %1; cvt.u32.u64 %0, t; }"
        : "=r"(a) : "l"(p));
    return a;
}

#define CP16(dst, src) \
    asm volatile("cp.async.cg.shared.global [%0], [%1], 16;" \
                 :: "r"(dst), "l"(src) : "memory")
#define CP_COMMIT() asm volatile("cp.async.commit_group;" ::: "memory")
#define CP_WAIT(n)  asm volatile("cp.async.wait_group %0;" :: "n"(n) : "memory")

#define LDSM_X4(r0, r1, r2, r3, addr)                                       \
    asm volatile("ldmatrix.sync.aligned.m8n8.x4.shared.b16 "                \
                 "{%0,%1,%2,%3}, [%4];"                                     \
                 : "=r"(r0), "=r"(r1), "=r"(r2), "=r"(r3) : "r"(addr))

#define MMA16816(d0, d1, d2, d3, a0, a1, a2, a3, b0, b1)                    \
    asm volatile("mma.sync.aligned.m16n8k16.row.col.f32.f16.f16.f32 "       \
                 "{%0,%1,%2,%3}, {%4,%5,%6,%7}, {%8,%9}, {%0,%1,%2,%3};"    \
                 : "+f"(d0), "+f"(d1), "+f"(d2), "+f"(d3)                   \
                 : "r"(a0), "r"(a1), "r"(a2), "r"(a3), "r"(b0), "r"(b1))

__global__ __launch_bounds__(256, 2)
void gemm_mma_kernel(const float* __restrict__ bias, float* __restrict__ out) {
    extern __shared__ char smem[];
    GDC_WAIT();   // PDL: prelude results visible after this
    if ((int)blockIdx.x >= g_ntiles) return;
    const int t = g_tiles[blockIdx.x];
    const int c = t & 31;
    const int m0 = ((t >> 8) & 0xFF) * TILE_M;
    const int rows = (t >> 16) & 0xFF;
    const int base = g_offset[c] + m0;
    const int n0 = blockIdx.y * TILE_N;

    const int tid = threadIdx.x;
    const int wid = tid >> 5;
    const int lane = tid & 31;
    const int wm = wid >> 2;      // 0..1, 32 rows each
    const int wn = wid & 3;       // 0..3, 32 cols each

    int* s_row = (int*)(smem + OFF_ROW);
    float* s_bias = (float*)(smem + OFF_BIAS);
    const uint32_t sb = smem_u32(smem);

    if (tid < TILE_M) s_row[tid] = g_perm[base + min(tid, rows - 1)];
    if (tid < TILE_N) s_bias[tid] = bias[(size_t)(n0 + tid) * C_SZ + c];

    const __half* wsrc0 = g_wq + ((size_t)c << 16) + (size_t)n0 * I_SZ;

    // ---- W loads first (independent of s_row) ----
#pragma unroll
    for (int kc = 0; kc < 4; kc++) {
        const uint32_t dstW = sb + OFF_PIPE + kc * STAGE + A_CH;
        const __half* sw = wsrc0 + kc * 64;
#pragma unroll
        for (int it = 0; it < 4; it++) {
            int task = tid + it * 256;
            int r = task >> 3, g = task & 7;
            uint32_t soff = r * RB + ((g ^ (r & 7)) << 4);
            CP16(dstW + soff, sw + (size_t)r * I_SZ + g * 8);
        }
    }
    __syncthreads();   // publish s_row (W issue hid the perm-load latency)

    // ---- A loads: one commit group per K-chunk (W kc goes in group kc) ----
#pragma unroll
    for (int kc = 0; kc < 4; kc++) {
        const uint32_t dstA = sb + OFF_PIPE + kc * STAGE;
        const int ko = kc * 64;
#pragma unroll
        for (int it = 0; it < 2; it++) {
            int task = tid + it * 256;
            int r = task >> 3, g = task & 7;
            uint32_t soff = r * RB + ((g ^ (r & 7)) << 4);
            CP16(dstA + soff, g_xh + (size_t)s_row[r] * I_SZ + ko + g * 8);
        }
        CP_COMMIT();
    }

    float acc[2][4][4];
#pragma unroll
    for (int i = 0; i < 2; i++)
#pragma unroll
        for (int j = 0; j < 4; j++)
#pragma unroll
            for (int q = 0; q < 4; q++) acc[i][j][q] = 0.0f;

    uint32_t arow[2], brow[2];
    const int ahi = lane >> 4;
    const int bhi = (lane >> 3) & 1;
#pragma unroll
    for (int mt = 0; mt < 2; mt++)
        arow[mt] = wm * 32 + mt * 16 + (lane & 15);
#pragma unroll
    for (int p = 0; p < 2; p++)
        brow[p] = wn * 32 + p * 16 + (lane >> 4) * 8 + (lane & 7);

    auto compute = [&](int kc) {
        const uint32_t ab = sb + OFF_PIPE + kc * STAGE;
        const uint32_t wb = ab + A_CH;
#pragma unroll
        for (int j = 0; j < 4; j++) {
            uint32_t a[2][4], b[2][4];
#pragma unroll
            for (int mt = 0; mt < 2; mt++) {
                uint32_t g = (uint32_t)(j * 2 + ahi);
                uint32_t addr = ab + arow[mt] * RB +
                                ((g ^ (arow[mt] & 7)) << 4);
                LDSM_X4(a[mt][0], a[mt][1], a[mt][2], a[mt][3], addr);
            }
#pragma unroll
            for (int p = 0; p < 2; p++) {
                uint32_t g = (uint32_t)(j * 2 + bhi);
                uint32_t addr = wb + brow[p] * RB +
                                ((g ^ (brow[p] & 7)) << 4);
                LDSM_X4(b[p][0], b[p][1], b[p][2], b[p][3], addr);
            }
#pragma unroll
            for (int mt = 0; mt < 2; mt++) {
#pragma unroll
                for (int nt = 0; nt < 4; nt++) {
                    uint32_t b0 = b[nt >> 1][(nt & 1) * 2 + 0];
                    uint32_t b1 = b[nt >> 1][(nt & 1) * 2 + 1];
                    MMA16816(acc[mt][nt][0], acc[mt][nt][1],
                             acc[mt][nt][2], acc[mt][nt][3],
                             a[mt][0], a[mt][1], a[mt][2], a[mt][3], b0, b1);
                }
            }
        }
    };

    // progressive consume: compute(k) overlaps in-flight later chunks
    CP_WAIT(3);
    __syncthreads();
    compute(0);
    CP_WAIT(2);
    __syncthreads();
    compute(1);
    CP_WAIT(1);
    __syncthreads();
    compute(2);
    CP_WAIT(0);
    __syncthreads();
    compute(3);

    // ---- epilogue ----
    const int g = lane >> 2, tq = lane & 3;
#pragma unroll
    for (int mt = 0; mt < 2; mt++) {
        int rl = wm * 32 + mt * 16 + g;
#pragma unroll
        for (int h = 0; h < 2; h++) {
            int rr = rl + h * 8;
            if (rr < rows) {
                float* op = out + (size_t)s_row[rr] * O_SZ + n0;
#pragma unroll
                for (int nt = 0; nt < 4; nt++) {
                    int cl = wn * 32 + nt * 8 + 2 * tq;
                    float2 v;
                    v.x = acc[mt][nt][h * 2 + 0] + s_bias[cl + 0];
                    v.y = acc[mt][nt][h * 2 + 1] + s_bias[cl + 1];
                    *(float2*)(op + cl) = v;
                }
            }
        }
    }
}

// ---------------------------------------------------------------------------
// launch: 2 kernels, GEMM launched with PDL so it overlaps the prelude tail
// ---------------------------------------------------------------------------
extern "C" void kernel_launch(void* const* d_in, const int* in_sizes, int n_in,
                              void* d_out, int out_size) {
    const float* x      = (const float*)d_in[0];
    const void*  idx    = d_in[1];
    const float* weight = (const float*)d_in[2];
    const float* bias   = (const float*)d_in[3];
    float* out = (float*)d_out;

    cudaFuncSetAttribute(gemm_mma_kernel,
                         cudaFuncAttributeMaxDynamicSharedMemorySize, SM_TOTAL);

    k_prelude<<<800, 256>>>(x, idx, weight);

    cudaLaunchConfig_t cfg = {};
    cfg.gridDim = dim3(MAX_TILES, O_SZ / TILE_N);
    cfg.blockDim = dim3(256);
    cfg.dynamicSmemBytes = SM_TOTAL;
    cfg.stream = 0;
    cudaLaunchAttribute attrs[1];
    attrs[0].id = cudaLaunchAttributeProgrammaticStreamSerialization;
    attrs[0].val.programmaticStreamSerializationAllowed = 1;
    cfg.attrs = attrs;
    cfg.numAttrs = 1;
    cudaLaunchKernelEx(&cfg, gemm_mma_kernel, bias, out);
}